// round 5
// baseline (speedup 1.0000x reference)
#include <cuda_runtime.h>
#include <cstdint>
#include <cstddef>

// ============================================================================
// RNNSequence: h_t = tanh(x_t @ W_ih + h_{t-1} @ W_hh + b), out[b,t,:] = h_t
// B=32, T=2048, D_IN=512, D_H=512, fp32.
//
// Phase 1: gemm_xw writes xw = x@W_ih + b into d_out (65536x512, f32x2 FMA).
// Phase 2: rnn_scan: 32 clusters x 2 CTAs (1024 thr), ONE batch per cluster.
//          CTA rank r owns output cols [256r,256r+256). W_hh slice entirely
//          in registers (64 f32x2/thread). Per step: read h from smem
//          (broadcast), FMA, 4-lane shuffle reduce, tanh, scatter 1 float to
//          both CTAs' next h buffer, one 2-CTA barrier.cluster.
// ============================================================================

constexpr int SEQ = 2048;
constexpr int DH  = 512;

__device__ __forceinline__ unsigned long long pack2(float lo, float hi) {
    unsigned long long r;
    unsigned l = __float_as_uint(lo), h = __float_as_uint(hi);
    asm("mov.b64 %0, {%1, %2};" : "=l"(r) : "r"(l), "r"(h));
    return r;
}
__device__ __forceinline__ void unpack2(unsigned long long v, float& lo, float& hi) {
    unsigned l, h;
    asm("mov.b64 {%0, %1}, %2;" : "=r"(l), "=r"(h) : "l"(v));
    lo = __uint_as_float(l);
    hi = __uint_as_float(h);
}
__device__ __forceinline__ void fma2(unsigned long long& acc,
                                     unsigned long long a, unsigned long long b) {
    asm("fma.rn.f32x2 %0, %1, %2, %0;" : "+l"(acc) : "l"(a), "l"(b));
}

// ---------------------------------------------------------------------------
// Phase 1: C[M,512] = A[M,512] @ B[512,512] + bias  (128x128x16, f32x2)
// ---------------------------------------------------------------------------
__global__ __launch_bounds__(256, 2) void gemm_xw(const float* __restrict__ A,
                                                  const float* __restrict__ B,
                                                  const float* __restrict__ bias,
                                                  float* __restrict__ C) {
    constexpr int K = 512, N = 512;
    __shared__ __align__(16) float As[16][128];
    __shared__ __align__(16) float Bs[16][128];

    const int tid  = threadIdx.x;
    const int row0 = blockIdx.y * 128;
    const int col0 = blockIdx.x * 128;
    const int ty   = tid >> 4;
    const int tx   = tid & 15;

    unsigned long long acc2[8][4];
#pragma unroll
    for (int i = 0; i < 8; i++)
#pragma unroll
        for (int j = 0; j < 4; j++) acc2[i][j] = 0ULL;

    for (int k0 = 0; k0 < K; k0 += 16) {
#pragma unroll
        for (int i = 0; i < 2; i++) {
            int s  = tid + i * 256;
            int m  = s & 127;
            int kg = (s >> 7) << 2;
            float4 v = *(const float4*)(A + (size_t)(row0 + m) * K + (k0 + kg));
            As[kg + 0][m] = v.x;
            As[kg + 1][m] = v.y;
            As[kg + 2][m] = v.z;
            As[kg + 3][m] = v.w;
        }
#pragma unroll
        for (int i = 0; i < 2; i++) {
            int s  = tid + i * 256;
            int n4 = (s & 31) << 2;
            int kk = s >> 5;
            *(float4*)(&Bs[kk][n4]) =
                *(const float4*)(B + (size_t)(k0 + kk) * N + col0 + n4);
        }
        __syncthreads();

#pragma unroll
        for (int kk = 0; kk < 16; kk++) {
            float a[8];
            *(float4*)(a)     = *(const float4*)(&As[kk][ty * 8]);
            *(float4*)(a + 4) = *(const float4*)(&As[kk][ty * 8 + 4]);
            ulonglong2 b01 = *(const ulonglong2*)(&Bs[kk][tx * 8]);
            ulonglong2 b23 = *(const ulonglong2*)(&Bs[kk][tx * 8 + 4]);
            unsigned long long bb[4] = {b01.x, b01.y, b23.x, b23.y};
#pragma unroll
            for (int i = 0; i < 8; i++) {
                unsigned au = __float_as_uint(a[i]);
                unsigned long long ad;
                asm("mov.b64 %0, {%1, %1};" : "=l"(ad) : "r"(au));
#pragma unroll
                for (int j2 = 0; j2 < 4; j2++) fma2(acc2[i][j2], ad, bb[j2]);
            }
        }
        __syncthreads();
    }

    float bv[8];
    *(float4*)(bv)     = *(const float4*)(bias + col0 + tx * 8);
    *(float4*)(bv + 4) = *(const float4*)(bias + col0 + tx * 8 + 4);

#pragma unroll
    for (int i = 0; i < 8; i++) {
        float o[8];
#pragma unroll
        for (int j2 = 0; j2 < 4; j2++) {
            float lo, hi;
            unpack2(acc2[i][j2], lo, hi);
            o[j2 * 2]     = lo + bv[j2 * 2];
            o[j2 * 2 + 1] = hi + bv[j2 * 2 + 1];
        }
        float* cp = C + (size_t)(row0 + ty * 8 + i) * N + col0 + tx * 8;
        *(float4*)(cp)     = *(float4*)(o);
        *(float4*)(cp + 4) = *(float4*)(o + 4);
    }
}

// ---------------------------------------------------------------------------
// Phase 2: 2-CTA clusters, W in registers
// ---------------------------------------------------------------------------
constexpr int HCH = 136;                 // padded per-kq chunk stride (floats)

__device__ __forceinline__ uint32_t smem_u32(const void* p) {
    return (uint32_t)__cvta_generic_to_shared(p);
}

// Precise tanh robust to --use_fast_math (expm1f is never substituted).
__device__ __forceinline__ float tanh_precise(float x) {
    float ax = fabsf(x);
    float em = expm1f(-2.0f * ax);
    float r  = -em / (2.0f + em);
    return copysignf(r, x);
}

__device__ __forceinline__ void st_cluster_f32(uint32_t raddr, float v) {
    asm volatile("st.shared::cluster.f32 [%0], %1;"
                 :: "r"(raddr), "f"(v) : "memory");
}

__global__ __launch_bounds__(1024, 1) void rnn_scan(float* __restrict__ out,
                                                    const float* __restrict__ Whh) {
    // h double buffer: [buf][4 chunks of 128, stride HCH]
    __shared__ __align__(16) float hbuf[2][4 * HCH];

    const int tid = threadIdx.x;
    const int r   = blockIdx.x & 1;    // rank in cluster (0/1)
    const int c   = blockIdx.x >> 1;   // cluster id == batch (0..31)

    const int j   = tid >> 2;          // 0..255 column within slice
    const int kq  = tid & 3;           // 0..3 k-quarter
    const int col = r * 256 + j;       // global output column
    const int k0  = kq * 128;

    // W_hh slice in registers: w2[i] = (Whh[k0+2i][col], Whh[k0+2i+1][col])
    unsigned long long w2[64];
#pragma unroll
    for (int i = 0; i < 64; i++) {
        float lo = Whh[(size_t)(k0 + 2 * i)     * 512 + col];
        float hi = Whh[(size_t)(k0 + 2 * i + 1) * 512 + col];
        w2[i] = pack2(lo, hi);
    }

    for (int idx = tid; idx < 2 * 4 * HCH; idx += 1024)
        ((float*)hbuf)[idx] = 0.0f;
    __syncthreads();
    asm volatile("barrier.cluster.arrive.aligned;" ::: "memory");
    asm volatile("barrier.cluster.wait.aligned;"   ::: "memory");

    // Peer hbuf base addresses (rank 0 and 1; includes self).
    const uint32_t hbB = smem_u32(hbuf);
    uint32_t peer_h[2];
#pragma unroll
    for (int p = 0; p < 2; p++)
        asm("mapa.shared::cluster.u32 %0, %1, %2;"
            : "=r"(peer_h[p]) : "r"(hbB), "r"(p));

    float* outp = out + ((size_t)c * SEQ) * DH + col;
    // scatter target byte offset within a buffer: chunk (col>>7), pos (col&127)
    const uint32_t hoff = (uint32_t)((col >> 7) * HCH + (col & 127)) * 4;
    constexpr uint32_t BUFB = 4 * HCH * 4;   // bytes per buffer

    for (int t = 0; t < SEQ; ++t) {
        const int cur = t & 1;
        const int nb  = cur ^ 1;

        // prefetch xw[c,t,col] (writer lanes only); hidden under FMA work
        float xwv = 0.0f;
        if (kq == 0) xwv = __ldg(outp + (size_t)t * DH);

        const ulonglong2* hc = (const ulonglong2*)&hbuf[cur][kq * HCH];

        unsigned long long a0 = 0ULL, a1 = 0ULL;
#pragma unroll
        for (int i = 0; i < 32; i += 2) {
            ulonglong2 x0 = hc[i];
            ulonglong2 x1 = hc[i + 1];
            fma2(a0, w2[2 * i],     x0.x);
            fma2(a0, w2[2 * i + 1], x0.y);
            fma2(a1, w2[2 * i + 2], x1.x);
            fma2(a1, w2[2 * i + 3], x1.y);
        }
        float l0, h0, l1, h1;
        unpack2(a0, l0, h0);
        unpack2(a1, l1, h1);
        float pS = (l0 + h0) + (l1 + h1);
        // reduce over the 4 kq lanes (adjacent lanes, same column)
        pS += __shfl_xor_sync(0xffffffffu, pS, 1);
        pS += __shfl_xor_sync(0xffffffffu, pS, 2);

        if (kq == 0) {
            float hn = tanh_precise(pS + xwv);
            outp[(size_t)t * DH] = hn;
            if (t < SEQ - 1) {
                uint32_t doff = (uint32_t)nb * BUFB + hoff;
                st_cluster_f32(peer_h[0] + doff, hn);
                st_cluster_f32(peer_h[1] + doff, hn);
            }
        }

        if (t < SEQ - 1) {
            // Release our scatter stores / acquire peer's (aligned cluster
            // barrier has acq_rel semantics); also orders local smem.
            asm volatile("barrier.cluster.arrive.aligned;" ::: "memory");
            asm volatile("barrier.cluster.wait.aligned;"   ::: "memory");
        }
    }

    // Exit safety: last step issued no remote ops after the final barrier.
    asm volatile("barrier.cluster.arrive.aligned;" ::: "memory");
    asm volatile("barrier.cluster.wait.aligned;"   ::: "memory");
}

// ---------------------------------------------------------------------------
// Launch
// ---------------------------------------------------------------------------
extern "C" void kernel_launch(void* const* d_in, const int* in_sizes, int n_in,
                              void* d_out, int out_size) {
    const float* x    = (const float*)d_in[0];  // [32,2048,512]
    const float* W_ih = (const float*)d_in[1];  // [512,512]
    const float* W_hh = (const float*)d_in[2];  // [512,512]
    const float* bias = (const float*)d_in[3];  // [512]
    float* out = (float*)d_out;                 // [32,2048,512]

    dim3 ggrid(512 / 128, (32 * SEQ) / 128);    // (4, 512)
    gemm_xw<<<ggrid, 256>>>(x, W_ih, bias, out);

    cudaLaunchConfig_t cfg = {};
    cfg.gridDim          = dim3(64, 1, 1);      // 32 clusters x 2 CTAs
    cfg.blockDim         = dim3(1024, 1, 1);
    cfg.dynamicSmemBytes = 0;
    cfg.stream           = 0;

    cudaLaunchAttribute attrs[1];
    attrs[0].id = cudaLaunchAttributeClusterDimension;
    attrs[0].val.clusterDim.x = 2;
    attrs[0].val.clusterDim.y = 1;
    attrs[0].val.clusterDim.z = 1;
    cfg.attrs    = attrs;
    cfg.numAttrs = 1;

    cudaLaunchKernelEx(&cfg, rnn_scan, out, W_hh);
}

// round 6
// speedup vs baseline: 1.6415x; 1.6415x over previous
#include <cuda_runtime.h>
#include <cstdint>
#include <cstddef>

// ============================================================================
// RNNSequence: h_t = tanh(x_t @ W_ih + h_{t-1} @ W_hh + b), out[b,t,:] = h_t
// B=32, T=2048, D_IN=512, D_H=512, fp32.
//
// Phase 1: gemm_xw writes xw = x@W_ih + b into d_out (65536x512, f32x2 FMA).
// Phase 2: rnn_scan: 16 clusters x 8 CTAs x 256 thr, batches {2c,2c+1}.
//          W_hh slice in registers (64 f32x2/thread, 188 regs total).
//          Exchange: stage 128 h values locally, then ONE st.shared::cluster
//          .v4.f32 per thread (256 x 16B packets vs 1024 x 4B) + one
//          barrier.cluster per step. xw prefetched one step ahead.
// ============================================================================

constexpr int SEQ = 2048;
constexpr int DH  = 512;

__device__ __forceinline__ unsigned long long pack2(float lo, float hi) {
    unsigned long long r;
    unsigned l = __float_as_uint(lo), h = __float_as_uint(hi);
    asm("mov.b64 %0, {%1, %2};" : "=l"(r) : "r"(l), "r"(h));
    return r;
}
__device__ __forceinline__ void unpack2(unsigned long long v, float& lo, float& hi) {
    unsigned l, h;
    asm("mov.b64 {%0, %1}, %2;" : "=r"(l), "=r"(h) : "l"(v));
    lo = __uint_as_float(l);
    hi = __uint_as_float(h);
}
__device__ __forceinline__ void fma2(unsigned long long& acc,
                                     unsigned long long a, unsigned long long b) {
    asm("fma.rn.f32x2 %0, %1, %2, %0;" : "+l"(acc) : "l"(a), "l"(b));
}

// ---------------------------------------------------------------------------
// Phase 1: C[M,512] = A[M,512] @ B[512,512] + bias  (128x128x16, f32x2)
// ---------------------------------------------------------------------------
__global__ __launch_bounds__(256, 2) void gemm_xw(const float* __restrict__ A,
                                                  const float* __restrict__ B,
                                                  const float* __restrict__ bias,
                                                  float* __restrict__ C) {
    constexpr int K = 512, N = 512;
    __shared__ __align__(16) float As[16][128];
    __shared__ __align__(16) float Bs[16][128];

    const int tid  = threadIdx.x;
    const int row0 = blockIdx.y * 128;
    const int col0 = blockIdx.x * 128;
    const int ty   = tid >> 4;
    const int tx   = tid & 15;

    unsigned long long acc2[8][4];
#pragma unroll
    for (int i = 0; i < 8; i++)
#pragma unroll
        for (int j = 0; j < 4; j++) acc2[i][j] = 0ULL;

    for (int k0 = 0; k0 < K; k0 += 16) {
#pragma unroll
        for (int i = 0; i < 2; i++) {
            int s  = tid + i * 256;
            int m  = s & 127;
            int kg = (s >> 7) << 2;
            float4 v = *(const float4*)(A + (size_t)(row0 + m) * K + (k0 + kg));
            As[kg + 0][m] = v.x;
            As[kg + 1][m] = v.y;
            As[kg + 2][m] = v.z;
            As[kg + 3][m] = v.w;
        }
#pragma unroll
        for (int i = 0; i < 2; i++) {
            int s  = tid + i * 256;
            int n4 = (s & 31) << 2;
            int kk = s >> 5;
            *(float4*)(&Bs[kk][n4]) =
                *(const float4*)(B + (size_t)(k0 + kk) * N + col0 + n4);
        }
        __syncthreads();

#pragma unroll
        for (int kk = 0; kk < 16; kk++) {
            float a[8];
            *(float4*)(a)     = *(const float4*)(&As[kk][ty * 8]);
            *(float4*)(a + 4) = *(const float4*)(&As[kk][ty * 8 + 4]);
            ulonglong2 b01 = *(const ulonglong2*)(&Bs[kk][tx * 8]);
            ulonglong2 b23 = *(const ulonglong2*)(&Bs[kk][tx * 8 + 4]);
            unsigned long long bb[4] = {b01.x, b01.y, b23.x, b23.y};
#pragma unroll
            for (int i = 0; i < 8; i++) {
                unsigned au = __float_as_uint(a[i]);
                unsigned long long ad;
                asm("mov.b64 %0, {%1, %1};" : "=l"(ad) : "r"(au));
#pragma unroll
                for (int j2 = 0; j2 < 4; j2++) fma2(acc2[i][j2], ad, bb[j2]);
            }
        }
        __syncthreads();
    }

    float bv[8];
    *(float4*)(bv)     = *(const float4*)(bias + col0 + tx * 8);
    *(float4*)(bv + 4) = *(const float4*)(bias + col0 + tx * 8 + 4);

#pragma unroll
    for (int i = 0; i < 8; i++) {
        float o[8];
#pragma unroll
        for (int j2 = 0; j2 < 4; j2++) {
            float lo, hi;
            unpack2(acc2[i][j2], lo, hi);
            o[j2 * 2]     = lo + bv[j2 * 2];
            o[j2 * 2 + 1] = hi + bv[j2 * 2 + 1];
        }
        float* cp = C + (size_t)(row0 + ty * 8 + i) * N + col0 + tx * 8;
        *(float4*)(cp)     = *(float4*)(o);
        *(float4*)(cp + 4) = *(float4*)(o + 4);
    }
}

// ---------------------------------------------------------------------------
// Phase 2: 8-CTA clusters, W in registers, vectorized DSMEM exchange
// ---------------------------------------------------------------------------
constexpr int HCH  = 136;                // padded per-kq chunk stride (floats)
constexpr int HBAT = 4 * HCH;            // 544 floats per (buf,batch)
constexpr uint32_t BUFB = (uint32_t)(2 * HBAT) * 4;   // bytes per buffer

__device__ __forceinline__ uint32_t smem_u32(const void* p) {
    return (uint32_t)__cvta_generic_to_shared(p);
}

// Precise tanh robust to --use_fast_math (expm1f is never substituted).
__device__ __forceinline__ float tanh_precise(float x) {
    float ax = fabsf(x);
    float em = expm1f(-2.0f * ax);
    float r  = -em / (2.0f + em);
    return copysignf(r, x);
}

__device__ __forceinline__ void st_cluster_v4(uint32_t raddr, float4 v) {
    asm volatile("st.shared::cluster.v4.f32 [%0], {%1, %2, %3, %4};"
                 :: "r"(raddr), "f"(v.x), "f"(v.y), "f"(v.z), "f"(v.w)
                 : "memory");
}

__global__ __launch_bounds__(256, 1) void rnn_scan(float* __restrict__ out,
                                                   const float* __restrict__ Whh) {
    __shared__ __align__(16) float hbuf[2][2][HBAT];
    __shared__ __align__(16) float staged[2][64];   // [batch][j] this CTA's slice

    const int tid   = threadIdx.x;
    const int r     = blockIdx.x & 7;    // rank in cluster
    const int c     = blockIdx.x >> 3;   // cluster id (0..15)
    const int jbase = r * 64;

    const int j   = tid >> 2;            // 0..63
    const int kq  = tid & 3;             // 0..3
    const int col = jbase + j;
    const int k0  = kq * 128;

    // W_hh slice in registers: w2[i] = (Whh[k0+2i][col], Whh[k0+2i+1][col])
    unsigned long long w2[64];
#pragma unroll
    for (int i = 0; i < 64; i++) {
        float lo = Whh[(size_t)(k0 + 2 * i)     * 512 + col];
        float hi = Whh[(size_t)(k0 + 2 * i + 1) * 512 + col];
        w2[i] = pack2(lo, hi);
    }

    for (int idx = tid; idx < 2 * 2 * HBAT; idx += 256)
        ((float*)hbuf)[idx] = 0.0f;
    __syncthreads();
    asm volatile("barrier.cluster.arrive.aligned;" ::: "memory");
    asm volatile("barrier.cluster.wait.aligned;"   ::: "memory");

    // Peer hbuf addresses
    const uint32_t hbB = smem_u32(hbuf);
    uint32_t peer_h[8];
#pragma unroll
    for (int p = 0; p < 8; p++)
        asm("mapa.shared::cluster.u32 %0, %1, %2;"
            : "=r"(peer_h[p]) : "r"(hbB), "r"(p));

    // writer role: kq==0 -> batch 2c, kq==1 -> batch 2c+1
    const int batch = (kq < 2) ? kq : 0;
    const int gj    = jbase + j;
    float* outp = out + ((size_t)(c * 2 + batch) * SEQ) * DH + gj;

    // Exchange role: thread -> (peer, float4 index)
    const int ep   = tid >> 5;           // peer 0..7
    const int ef   = tid & 31;           // float4 idx 0..31 (bsel*16 + q)
    const int ebs  = ef >> 4;            // batch select
    const int eq   = ef & 15;            // float4 within slice
    // Destination: peer's hbuf[nb][ebs] at OUR slice (cols jbase..jbase+63)
    const uint32_t sliceoff =
        (uint32_t)((jbase >> 7) * HCH + (jbase & 127));   // floats
    const uint32_t edst_base =
        peer_h[ep] + ((uint32_t)ebs * HBAT + sliceoff + (uint32_t)eq * 4) * 4;

    // xw prefetch pipeline (one step ahead)
    float xw_next = 0.0f;
    if (kq < 2) xw_next = __ldg(outp);

    for (int t = 0; t < SEQ; ++t) {
        const int cur = t & 1;
        const int nb  = cur ^ 1;

        float xwv = xw_next;
        if (kq < 2 && t + 1 < SEQ) xw_next = __ldg(outp + (size_t)(t + 1) * DH);

        const ulonglong2* hA = (const ulonglong2*)&hbuf[cur][0][kq * HCH];
        const ulonglong2* hB = (const ulonglong2*)&hbuf[cur][1][kq * HCH];

        unsigned long long aA0 = 0ULL, aA1 = 0ULL, aB0 = 0ULL, aB1 = 0ULL;
#pragma unroll
        for (int i = 0; i < 32; i += 2) {
            ulonglong2 x0 = hA[i];
            ulonglong2 x1 = hA[i + 1];
            ulonglong2 y0 = hB[i];
            ulonglong2 y1 = hB[i + 1];
            fma2(aA0, w2[2 * i],     x0.x);
            fma2(aA0, w2[2 * i + 1], x0.y);
            fma2(aA1, w2[2 * i + 2], x1.x);
            fma2(aA1, w2[2 * i + 3], x1.y);
            fma2(aB0, w2[2 * i],     y0.x);
            fma2(aB0, w2[2 * i + 1], y0.y);
            fma2(aB1, w2[2 * i + 2], y1.x);
            fma2(aB1, w2[2 * i + 3], y1.y);
        }
        float a0l, a0h, a1l, a1h, b0l, b0h, b1l, b1h;
        unpack2(aA0, a0l, a0h);
        unpack2(aA1, a1l, a1h);
        unpack2(aB0, b0l, b0h);
        unpack2(aB1, b1l, b1h);
        float pA = (a0l + a0h) + (a1l + a1h);
        float pB = (b0l + b0h) + (b1l + b1h);
        pA += __shfl_xor_sync(0xffffffffu, pA, 1);
        pB += __shfl_xor_sync(0xffffffffu, pB, 1);
        pA += __shfl_xor_sync(0xffffffffu, pA, 2);
        pB += __shfl_xor_sync(0xffffffffu, pB, 2);

        if (kq < 2) {
            float s  = (kq == 0 ? pA : pB) + xwv;
            float hn = tanh_precise(s);
            outp[(size_t)t * DH] = hn;
            staged[kq][j] = hn;          // stage for vectorized exchange
        }

        if (t < SEQ - 1) {
            __syncthreads();             // staged[] complete, hbuf[cur] reads done
            // One 16B remote store per thread: 8 peers x 32 float4.
            float4 v = ((const float4*)staged)[ef];
            st_cluster_v4(edst_base + (uint32_t)nb * BUFB, v);
            // Release stores / acquire peers' stores.
            asm volatile("barrier.cluster.arrive.aligned;" ::: "memory");
            asm volatile("barrier.cluster.wait.aligned;"   ::: "memory");
        }
    }

    // Keep SMEM alive until all cluster CTAs are done with remote ops.
    asm volatile("barrier.cluster.arrive.aligned;" ::: "memory");
    asm volatile("barrier.cluster.wait.aligned;"   ::: "memory");
}

// ---------------------------------------------------------------------------
// Launch
// ---------------------------------------------------------------------------
extern "C" void kernel_launch(void* const* d_in, const int* in_sizes, int n_in,
                              void* d_out, int out_size) {
    const float* x    = (const float*)d_in[0];  // [32,2048,512]
    const float* W_ih = (const float*)d_in[1];  // [512,512]
    const float* W_hh = (const float*)d_in[2];  // [512,512]
    const float* bias = (const float*)d_in[3];  // [512]
    float* out = (float*)d_out;                 // [32,2048,512]

    dim3 ggrid(512 / 128, (32 * SEQ) / 128);    // (4, 512)
    gemm_xw<<<ggrid, 256>>>(x, W_ih, bias, out);

    cudaLaunchConfig_t cfg = {};
    cfg.gridDim          = dim3(128, 1, 1);     // 16 clusters x 8 CTAs
    cfg.blockDim         = dim3(256, 1, 1);
    cfg.dynamicSmemBytes = 0;
    cfg.stream           = 0;

    cudaLaunchAttribute attrs[1];
    attrs[0].id = cudaLaunchAttributeClusterDimension;
    attrs[0].val.clusterDim.x = 8;
    attrs[0].val.clusterDim.y = 1;
    attrs[0].val.clusterDim.z = 1;
    cfg.attrs    = attrs;
    cfg.numAttrs = 1;

    cudaLaunchKernelEx(&cfg, rnn_scan, out, W_hh);
}